// round 13
// baseline (speedup 1.0000x reference)
#include <cuda_runtime.h>
#include <cuda_fp16.h>
#include <cuda_bf16.h>
#include <math.h>

#define BB 4
#define NN 2048
#define DD 512
#define KC 1536                        // concat K = 3*DD for split-bf16 GEMM
#define REG 0.1f
#define NITER 20
#define BPB 64
#define GRID (BB*BPB)

#define FI 0.83333333333333337f
#define A0 (1.0f/2048.0f)
#define V0 (1.0f/2048.0f)

#define SSTR 24                        // smem row stride (bf16 elems): conflict-free LDSM

// ---------------- scratch ----------------------------------------------------
__device__ __nv_bfloat16 g_xc[(size_t)BB*NN*KC];  // [xh | xl | xh]
__device__ __nv_bfloat16 g_yc[(size_t)BB*NN*KC];  // [yh | yh | yl]
__device__ float  g_x2[BB*NN];
__device__ float  g_y2[BB*NN];
__device__ float  g_K  [(size_t)BB*NN*NN];  // fp32 cost (cost_mma -> exp only)
__device__ __half g_Kh [(size_t)BB*NN*NN];  // fp16 K (sinkhorn + output)
__device__ float  g_part[(size_t)BB*BPB*NN];
__device__ float  g_u [BB*NN];
__device__ float  g_v [BB*NN];
__device__ unsigned int g_maxbits[BB];
__device__ unsigned int g_barB[BB];

// ---------------- init -------------------------------------------------------
__global__ void init_kernel() {
    int i = blockIdx.x * blockDim.x + threadIdx.x;
    if (i < BB) { g_maxbits[i] = 0u; g_barB[i] = 0u; }
    if (i < BB*NN) g_v[i] = V0;
}

// -------- per-row min-shift + sumsq + bf16 hi/lo split ------------------------
__global__ void normalize_rows(const float* __restrict__ src, int sel) {
    int row = blockIdx.x;
    const float* r = src + (size_t)row * DD;
    __nv_bfloat16* cat = (sel ? g_yc : g_xc) + (size_t)row * KC;
    float* sq = (sel ? g_y2 : g_x2);
    int t = threadIdx.x;
    float v[4];
    float mn = 3.0e38f;
    #pragma unroll
    for (int k = 0; k < 4; k++) { v[k] = r[t + 128*k]; mn = fminf(mn, v[k]); }
    #pragma unroll
    for (int off = 16; off; off >>= 1) mn = fminf(mn, __shfl_xor_sync(0xffffffffu, mn, off));
    __shared__ float smn[4];
    __shared__ float sss[4];
    int w = t >> 5;
    if ((t & 31) == 0) smn[w] = mn;
    __syncthreads();
    mn = fminf(fminf(smn[0], smn[1]), fminf(smn[2], smn[3]));
    float ss = 0.f;
    #pragma unroll
    for (int k = 0; k < 4; k++) {
        float z = v[k] - mn;
        ss += z*z;
        __nv_bfloat16 hi = __float2bfloat16(z);
        __nv_bfloat16 lo = __float2bfloat16(z - __bfloat162float(hi));
        int col = t + 128*k;
        if (sel == 0) { cat[col] = hi; cat[DD + col] = lo; cat[2*DD + col] = hi; }
        else          { cat[col] = hi; cat[DD + col] = hi; cat[2*DD + col] = lo; }
    }
    #pragma unroll
    for (int off = 16; off; off >>= 1) ss += __shfl_xor_sync(0xffffffffu, ss, off);
    if ((t & 31) == 0) sss[w] = ss;
    __syncthreads();
    if (t == 0) sq[row] = sss[0] + sss[1] + sss[2] + sss[3];
}

// -------- cost GEMM via mma.sync bf16 (split-precision, K=1536) --------------
// block 128x128, 4 warps (2x2) of 64x64, k-step 16, double-buffered smem.
// Same k-chunk order as previous kernel -> bit-identical accumulation.
__global__ __launch_bounds__(128) void cost_mma_kernel() {
    __shared__ __align__(16) unsigned short sA[2][128*SSTR];
    __shared__ __align__(16) unsigned short sB[2][128*SSTR];
    int b    = blockIdx.z;
    int col0 = blockIdx.x * 128;
    int row0 = blockIdx.y * 128;
    int t    = threadIdx.x;
    int lane = t & 31, wid = t >> 5;
    int warpM = wid >> 1, warpN = wid & 1;   // 2 x 2, warp tile 64x64
    int g = lane >> 2, tig = lane & 3;

    const __nv_bfloat16* Agl = g_xc + (size_t)(b*NN + row0) * KC;
    const __nv_bfloat16* Bgl = g_yc + (size_t)(b*NN + col0) * KC;

    // staging: thread t owns row t (both 8-elem k-halves)
    const uint4* Ap = (const uint4*)(Agl + (size_t)t * KC);
    const uint4* Bp = (const uint4*)(Bgl + (size_t)t * KC);
    unsigned short* sAdst = &sA[0][0] + t*SSTR;
    unsigned short* sBdst = &sB[0][0] + t*SSTR;

    // ldmatrix lane base offsets
    int arow = warpM*64 + (lane & 7) + ((lane >> 3) & 1) * 8;
    int acol = (lane >> 4) * 8;
    unsigned aoff0 = (unsigned)__cvta_generic_to_shared(&sA[0][0]) + (arow*SSTR + acol)*2;
    int brow = warpN*64 + (lane >> 4) * 8 + (lane & 7);
    int bcol = ((lane >> 3) & 1) * 8;
    unsigned boff0 = (unsigned)__cvta_generic_to_shared(&sB[0][0]) + (brow*SSTR + bcol)*2;
    const unsigned STGB = 128*SSTR*2;

    float acc[4][8][4];
    #pragma unroll
    for (int a = 0; a < 4; a++)
        #pragma unroll
        for (int nb = 0; nb < 8; nb++)
            #pragma unroll
            for (int e = 0; e < 4; e++) acc[a][nb][e] = 0.f;

    // prologue: chunk 0 into stage 0
    uint4 av0 = Ap[0], av1 = Ap[1];
    uint4 bv0 = Bp[0], bv1 = Bp[1];
    *(uint4*)(sAdst)     = av0;
    *(uint4*)(sAdst + 8) = av1;
    *(uint4*)(sBdst)     = bv0;
    *(uint4*)(sBdst + 8) = bv1;
    __syncthreads();

    const int NK = KC / 16;    // 96
    for (int c = 0; c < NK; c++) {
        int cur = c & 1, nxt = cur ^ 1;
        if (c + 1 < NK) {
            av0 = Ap[(c+1)*2];   av1 = Ap[(c+1)*2 + 1];
            bv0 = Bp[(c+1)*2];   bv1 = Bp[(c+1)*2 + 1];
        }
        unsigned abase = aoff0 + cur*STGB;
        unsigned bbase = boff0 + cur*STGB;

        unsigned afr[4][4], bfr[4][4];
        #pragma unroll
        for (int a = 0; a < 4; a++) {
            unsigned ad = abase + a*16*SSTR*2;
            asm volatile("ldmatrix.sync.aligned.m8n8.x4.shared.b16 {%0,%1,%2,%3}, [%4];"
                : "=r"(afr[a][0]), "=r"(afr[a][1]), "=r"(afr[a][2]), "=r"(afr[a][3])
                : "r"(ad));
        }
        #pragma unroll
        for (int p = 0; p < 4; p++) {
            unsigned bd = bbase + p*16*SSTR*2;
            asm volatile("ldmatrix.sync.aligned.m8n8.x4.shared.b16 {%0,%1,%2,%3}, [%4];"
                : "=r"(bfr[p][0]), "=r"(bfr[p][1]), "=r"(bfr[p][2]), "=r"(bfr[p][3])
                : "r"(bd));
        }
        #pragma unroll
        for (int a = 0; a < 4; a++)
            #pragma unroll
            for (int nb = 0; nb < 8; nb++) {
                int p = nb >> 1, h = nb & 1;
                asm volatile(
                    "mma.sync.aligned.m16n8k16.row.col.f32.bf16.bf16.f32 "
                    "{%0,%1,%2,%3}, {%4,%5,%6,%7}, {%8,%9}, {%0,%1,%2,%3};"
                    : "+f"(acc[a][nb][0]), "+f"(acc[a][nb][1]),
                      "+f"(acc[a][nb][2]), "+f"(acc[a][nb][3])
                    : "r"(afr[a][0]), "r"(afr[a][1]), "r"(afr[a][2]), "r"(afr[a][3]),
                      "r"(bfr[p][h*2]), "r"(bfr[p][h*2+1]));
            }

        if (c + 1 < NK) {
            *(uint4*)(sAdst + nxt*128*SSTR)     = av0;
            *(uint4*)(sAdst + nxt*128*SSTR + 8) = av1;
            *(uint4*)(sBdst + nxt*128*SSTR)     = bv0;
            *(uint4*)(sBdst + nxt*128*SSTR + 8) = bv1;
        }
        __syncthreads();
    }

    // epilogue: cost = max(x2 + y2 - 2*dot, 0)
    float lmax = 0.f;
    #pragma unroll
    for (int a = 0; a < 4; a++) {
        int m0 = row0 + warpM*64 + a*16 + g;
        float x2a = g_x2[b*NN + m0];
        float x2b = g_x2[b*NN + m0 + 8];
        #pragma unroll
        for (int nb = 0; nb < 8; nb++) {
            int n0 = col0 + warpN*64 + nb*8 + tig*2;
            float y20 = g_y2[b*NN + n0];
            float y21 = g_y2[b*NN + n0 + 1];
            float c0 = fmaxf(x2a + y20 - 2.0f*acc[a][nb][0], 0.f);
            float c1 = fmaxf(x2a + y21 - 2.0f*acc[a][nb][1], 0.f);
            float c2 = fmaxf(x2b + y20 - 2.0f*acc[a][nb][2], 0.f);
            float c3 = fmaxf(x2b + y21 - 2.0f*acc[a][nb][3], 0.f);
            lmax = fmaxf(lmax, fmaxf(fmaxf(c0, c1), fmaxf(c2, c3)));
            *(float2*)&g_K[(size_t)(b*NN + m0)     * NN + n0] = make_float2(c0, c1);
            *(float2*)&g_K[(size_t)(b*NN + m0 + 8) * NN + n0] = make_float2(c2, c3);
        }
    }
    #pragma unroll
    for (int off = 16; off; off >>= 1) lmax = fmaxf(lmax, __shfl_xor_sync(0xffffffffu, lmax, off));
    if (lane == 0) atomicMax(&g_maxbits[b], __float_as_uint(lmax));
}

// ------ K = exp(-cost/(reg*max)) -> fp16 only --------------------------------
__global__ void exp_half_kernel() {
    const int total4 = BB * NN * NN / 4;
    const int per_b4 = NN * NN / 4;
    const float4* K4 = (const float4*)g_K;
    for (int i = blockIdx.x * blockDim.x + threadIdx.x; i < total4;
         i += gridDim.x * blockDim.x) {
        int b = i / per_b4;
        float s = -1.0f / (REG * __uint_as_float(g_maxbits[b]));
        float4 v = K4[i];
        v.x = __expf(v.x * s);
        v.y = __expf(v.y * s);
        v.z = __expf(v.z * s);
        v.w = __expf(v.w * s);
        __half2 h0 = __floats2half2_rn(v.x, v.y);
        __half2 h1 = __floats2half2_rn(v.z, v.w);
        *(uint2*)&g_Kh[(size_t)i * 4] = make_uint2(
            *(unsigned int*)&h0, *(unsigned int*)&h1);
    }
}

// ---------------- per-batch grid barrier -------------------------------------
__device__ __forceinline__ void batch_bar(int b, unsigned int target) {
    __threadfence();
    __syncthreads();
    if (threadIdx.x == 0) {
        atomicAdd(&g_barB[b], 1u);
        while (*(volatile unsigned int*)&g_barB[b] < target) __nanosleep(32);
        __threadfence();
    }
    __syncthreads();
}

// ---------------- fused persistent sinkhorn ----------------------------------
__global__ __launch_bounds__(256, 2) void sinkhorn_kernel() {
    __shared__ float sv[NN];
    __shared__ float sp[64];
    __shared__ float su[16];
    __shared__ float syA[NN];
    __shared__ float spr[256];
    int b = blockIdx.x >> 6;
    int q = blockIdx.x & 63;
    int t = threadIdx.x;
    int lane = t & 31, w = t >> 5;
    int wg = w >> 2;
    int ws = w & 3;
    int jA = ws*512 + lane*8;

    const __half* Kh = g_Kh + (size_t)b * NN * NN;
    unsigned int target = 0;

    for (int it = 0; it < NITER; ++it) {
        for (int j = t; j < NN; j += 256) sv[j] = __ldcg(&g_v[b*NN + j]);
        __syncthreads();
        float2 vv[2][4];
        #pragma unroll
        for (int p = 0; p < 2; p++)
            #pragma unroll
            for (int c = 0; c < 4; c++)
                vv[p][c] = *(const float2*)&sv[jA + p*256 + c*2];

        float yac[16];
        #pragma unroll
        for (int k = 0; k < 16; k++) yac[k] = 0.f;

        for (int s = q; s < 128; s += BPB) {
            const __half* Krow = Kh + (size_t)(s*16 + wg*8) * NN + jA;

            float acc[8];
            #pragma unroll
            for (int r = 0; r < 8; r++) acc[r] = 0.f;
            #pragma unroll
            for (int r = 0; r < 8; r++) {
                #pragma unroll
                for (int p = 0; p < 2; p++) {
                    uint4 kk = *(const uint4*)(Krow + (size_t)r * NN + p*256);
                    const __half2* h = (const __half2*)&kk;
                    #pragma unroll
                    for (int c = 0; c < 4; c++) {
                        float2 kf = __half22float2(h[c]);
                        acc[r] = fmaf(kf.x, vv[p][c].x, acc[r]);
                        acc[r] = fmaf(kf.y, vv[p][c].y, acc[r]);
                    }
                }
            }
            #pragma unroll
            for (int r = 0; r < 8; r++) {
                float sm = acc[r];
                #pragma unroll
                for (int off = 16; off; off >>= 1) sm += __shfl_xor_sync(0xffffffffu, sm, off);
                if (lane == 0) sp[(wg*8 + r)*4 + ws] = sm;
            }
            __syncthreads();
            if (t < 16) {
                float tot = sp[t*4] + sp[t*4+1] + sp[t*4+2] + sp[t*4+3];
                float uu = powf(A0 / tot, FI);
                su[t] = uu;
                g_u[b*NN + s*16 + t] = uu;
            }
            __syncthreads();

            float ur[8];
            #pragma unroll
            for (int r = 0; r < 8; r++) ur[r] = su[wg*8 + r];
            #pragma unroll
            for (int r = 0; r < 8; r++) {
                #pragma unroll
                for (int p = 0; p < 2; p++) {
                    uint4 kk = *(const uint4*)(Krow + (size_t)r * NN + p*256);
                    const __half2* h = (const __half2*)&kk;
                    #pragma unroll
                    for (int c = 0; c < 4; c++) {
                        float2 kf = __half22float2(h[c]);
                        yac[p*8 + c*2]     = fmaf(kf.x, ur[r], yac[p*8 + c*2]);
                        yac[p*8 + c*2 + 1] = fmaf(kf.y, ur[r], yac[p*8 + c*2 + 1]);
                    }
                }
            }
        }

        if (wg == 1) {
            #pragma unroll
            for (int p = 0; p < 2; p++)
                #pragma unroll
                for (int c = 0; c < 4; c++)
                    *(float2*)&syA[jA + p*256 + c*2] = *(float2*)&yac[p*8 + c*2];
        }
        __syncthreads();
        if (wg == 0) {
            float* dst = g_part + ((size_t)(b*BPB + q)) * NN;
            #pragma unroll
            for (int p = 0; p < 2; p++)
                #pragma unroll
                for (int c = 0; c < 4; c++) {
                    int col = jA + p*256 + c*2;
                    float2 yy = *(float2*)&yac[p*8 + c*2];
                    float2 zz = *(float2*)&syA[col];
                    yy.x += zz.x; yy.y += zz.y;
                    *(float2*)&dst[col] = yy;
                }
        }
        target += BPB;
        batch_bar(b, target);

        {
            int col = q*32 + lane;
            float sm = 0.f;
            #pragma unroll
            for (int k = 0; k < 8; k++)
                sm += __ldcg(&g_part[((size_t)(b*BPB + w + 8*k)) * NN + col]);
            spr[w*32 + lane] = sm;
            __syncthreads();
            if (t < 32) {
                float tot = 0.f;
                #pragma unroll
                for (int p = 0; p < 8; p++) tot += spr[p*32 + t];
                g_v[b*NN + q*32 + t] = powf(A0 / tot, FI);
            }
        }
        target += BPB;
        batch_bar(b, target);
    }
}

// ------ out[b][j][i] = u[i] Kh[i][j] v[j]  (fp16 K read, 32x32 transpose) ----
__global__ void output_kernel(float* __restrict__ out) {
    __shared__ float tile[32][33];
    int b  = blockIdx.z;
    int j0 = blockIdx.x * 32;
    int i0 = blockIdx.y * 32;
    int tx = threadIdx.x, ty = threadIdx.y;
    const __half* Kb = g_Kh + (size_t)b * NN * NN;
    float vj = g_v[b*NN + j0 + tx];
    #pragma unroll
    for (int k = 0; k < 4; k++) {
        int i = i0 + ty + 8*k;
        float kij = __half2float(Kb[(size_t)i * NN + j0 + tx]);
        tile[ty + 8*k][tx] = kij * g_u[b*NN + i] * vj;
    }
    __syncthreads();
    #pragma unroll
    for (int k = 0; k < 4; k++) {
        int j = j0 + ty + 8*k;
        out[((size_t)b*NN + j) * NN + i0 + tx] = tile[tx][ty + 8*k];
    }
}

// ---------------- launch ------------------------------------------------------
extern "C" void kernel_launch(void* const* d_in, const int* in_sizes, int n_in,
                              void* d_out, int out_size) {
    const float* x = (const float*)d_in[0];
    const float* y = (const float*)d_in[1];
    float* out = (float*)d_out;

    init_kernel<<<(BB*NN + 255)/256, 256>>>();
    normalize_rows<<<BB*NN, 128>>>(x, 0);
    normalize_rows<<<BB*NN, 128>>>(y, 1);

    dim3 gcost(NN/128, NN/128, BB);
    cost_mma_kernel<<<gcost, 128>>>();

    exp_half_kernel<<<4096, 256>>>();

    sinkhorn_kernel<<<GRID, 256>>>();

    dim3 gout(NN/32, NN/32, BB);
    output_kernel<<<gout, dim3(32, 8)>>>(out);
}

// round 14
// speedup vs baseline: 1.0707x; 1.0707x over previous
#include <cuda_runtime.h>
#include <cuda_fp16.h>
#include <cuda_bf16.h>
#include <math.h>

#define BB 4
#define NN 2048
#define DD 512
#define KC 1536                        // concat K = 3*DD for split-bf16 GEMM
#define REG 0.1f
#define NITER 20
#define BPB 64
#define GRID (BB*BPB)

#define FI 0.83333333333333337f
#define A0 (1.0f/2048.0f)
#define V0 (1.0f/2048.0f)

#define SSTR 24                        // smem row stride (bf16 elems): conflict-free LDSM

// ---------------- scratch ----------------------------------------------------
__device__ __nv_bfloat16 g_xc[(size_t)BB*NN*KC];  // [xh | xl | xh]
__device__ __nv_bfloat16 g_yc[(size_t)BB*NN*KC];  // [yh | yh | yl]
__device__ float  g_x2[BB*NN];
__device__ float  g_y2[BB*NN];
__device__ float  g_K  [(size_t)BB*NN*NN];  // fp32 cost (cost_mma -> exp only)
__device__ __half g_Kh [(size_t)BB*NN*NN];  // fp16 K (sinkhorn + output)
__device__ float  g_part[(size_t)BB*BPB*NN];
__device__ float  g_u [BB*NN];
__device__ float  g_v [BB*NN];
__device__ unsigned int g_maxbits[BB];
__device__ unsigned int g_barB[BB];

// ---------------- init -------------------------------------------------------
__global__ void init_kernel() {
    int i = blockIdx.x * blockDim.x + threadIdx.x;
    if (i < BB) { g_maxbits[i] = 0u; g_barB[i] = 0u; }
    if (i < BB*NN) g_v[i] = V0;
}

// -------- per-row min-shift + sumsq + bf16 hi/lo split ------------------------
__global__ void normalize_rows(const float* __restrict__ src, int sel) {
    int row = blockIdx.x;
    const float* r = src + (size_t)row * DD;
    __nv_bfloat16* cat = (sel ? g_yc : g_xc) + (size_t)row * KC;
    float* sq = (sel ? g_y2 : g_x2);
    int t = threadIdx.x;
    float v[4];
    float mn = 3.0e38f;
    #pragma unroll
    for (int k = 0; k < 4; k++) { v[k] = r[t + 128*k]; mn = fminf(mn, v[k]); }
    #pragma unroll
    for (int off = 16; off; off >>= 1) mn = fminf(mn, __shfl_xor_sync(0xffffffffu, mn, off));
    __shared__ float smn[4];
    __shared__ float sss[4];
    int w = t >> 5;
    if ((t & 31) == 0) smn[w] = mn;
    __syncthreads();
    mn = fminf(fminf(smn[0], smn[1]), fminf(smn[2], smn[3]));
    float ss = 0.f;
    #pragma unroll
    for (int k = 0; k < 4; k++) {
        float z = v[k] - mn;
        ss += z*z;
        __nv_bfloat16 hi = __float2bfloat16(z);
        __nv_bfloat16 lo = __float2bfloat16(z - __bfloat162float(hi));
        int col = t + 128*k;
        if (sel == 0) { cat[col] = hi; cat[DD + col] = lo; cat[2*DD + col] = hi; }
        else          { cat[col] = hi; cat[DD + col] = hi; cat[2*DD + col] = lo; }
    }
    #pragma unroll
    for (int off = 16; off; off >>= 1) ss += __shfl_xor_sync(0xffffffffu, ss, off);
    if ((t & 31) == 0) sss[w] = ss;
    __syncthreads();
    if (t == 0) sq[row] = sss[0] + sss[1] + sss[2] + sss[3];
}

// -------- cost GEMM via mma.sync bf16 (split-precision, K=1536) --------------
// block 128x128, 8 warps (2x4) of 64x32, 32-col stages (2 chunks), ONE sync/stage.
// Chunk processing order identical to R12 -> bit-identical accumulation.
__global__ __launch_bounds__(256) void cost_mma_kernel() {
    // [stage][chunk] buffers
    __shared__ __align__(16) unsigned short sA[2][2][128*SSTR];
    __shared__ __align__(16) unsigned short sB[2][2][128*SSTR];
    int b    = blockIdx.z;
    int col0 = blockIdx.x * 128;
    int row0 = blockIdx.y * 128;
    int t    = threadIdx.x;
    int lane = t & 31, wid = t >> 5;
    int warpM = wid >> 2, warpN = wid & 3;   // 2 x 4, warp tile 64x32
    int g = lane >> 2, tig = lane & 3;

    const __nv_bfloat16* Agl = g_xc + (size_t)(b*NN + row0) * KC;
    const __nv_bfloat16* Bgl = g_yc + (size_t)(b*NN + col0) * KC;

    // staging: 2 threads per row; thread handles 8 bf16 (16B) per 16-col chunk
    int srow = t >> 1;
    int skof = (t & 1) * 8;
    const uint4* Ap = (const uint4*)(Agl + (size_t)srow * KC + skof);
    const uint4* Bp = (const uint4*)(Bgl + (size_t)srow * KC + skof);
    unsigned short* sAdst = &sA[0][0][0] + srow*SSTR + skof;
    unsigned short* sBdst = &sB[0][0][0] + srow*SSTR + skof;

    // ldmatrix lane base offsets (chunk 0 / stage 0)
    int arow = warpM*64 + (lane & 7) + ((lane >> 3) & 1) * 8;
    int acol = (lane >> 4) * 8;
    unsigned aoff0 = (unsigned)__cvta_generic_to_shared(&sA[0][0][0]) + (arow*SSTR + acol)*2;
    int brow = warpN*32 + (lane >> 4) * 8 + (lane & 7);
    int bcol = ((lane >> 3) & 1) * 8;
    unsigned boff0 = (unsigned)__cvta_generic_to_shared(&sB[0][0][0]) + (brow*SSTR + bcol)*2;
    const unsigned CHB = 128*SSTR*2;        // chunk stride (bytes / elems*2)
    const unsigned STB = 2*CHB;             // stage stride

    float acc[4][4][4];
    #pragma unroll
    for (int a = 0; a < 4; a++)
        #pragma unroll
        for (int nb = 0; nb < 4; nb++)
            #pragma unroll
            for (int e = 0; e < 4; e++) acc[a][nb][e] = 0.f;

    // prologue: stage 0 (chunks 0,1)
    {
        uint4 a0 = Ap[0], a1 = Ap[2];
        uint4 b0 = Bp[0], b1 = Bp[2];
        *(uint4*)(sAdst)                 = a0;
        *(uint4*)(sAdst + 128*SSTR)      = a1;
        *(uint4*)(sBdst)                 = b0;
        *(uint4*)(sBdst + 128*SSTR)      = b1;
    }
    __syncthreads();

    const int NS = KC / 32;    // 48 stages
    for (int c = 0; c < NS; c++) {
        int cur = c & 1, nxt = cur ^ 1;
        #pragma unroll
        for (int j = 0; j < 2; j++) {
            uint4 av, bv;
            if (c + 1 < NS) {               // prefetch next stage's chunk j
                av = Ap[(c+1)*4 + j*2];
                bv = Bp[(c+1)*4 + j*2];
            }
            unsigned abase = aoff0 + cur*STB + j*CHB;
            unsigned bbase = boff0 + cur*STB + j*CHB;

            unsigned afr[4][4], bfr[2][4];
            #pragma unroll
            for (int a = 0; a < 4; a++) {
                unsigned ad = abase + a*16*SSTR*2;
                asm volatile("ldmatrix.sync.aligned.m8n8.x4.shared.b16 {%0,%1,%2,%3}, [%4];"
                    : "=r"(afr[a][0]), "=r"(afr[a][1]), "=r"(afr[a][2]), "=r"(afr[a][3])
                    : "r"(ad));
            }
            #pragma unroll
            for (int p = 0; p < 2; p++) {
                unsigned bd = bbase + p*16*SSTR*2;
                asm volatile("ldmatrix.sync.aligned.m8n8.x4.shared.b16 {%0,%1,%2,%3}, [%4];"
                    : "=r"(bfr[p][0]), "=r"(bfr[p][1]), "=r"(bfr[p][2]), "=r"(bfr[p][3])
                    : "r"(bd));
            }
            #pragma unroll
            for (int a = 0; a < 4; a++)
                #pragma unroll
                for (int nb = 0; nb < 4; nb++) {
                    int p = nb >> 1, h = nb & 1;
                    asm volatile(
                        "mma.sync.aligned.m16n8k16.row.col.f32.bf16.bf16.f32 "
                        "{%0,%1,%2,%3}, {%4,%5,%6,%7}, {%8,%9}, {%0,%1,%2,%3};"
                        : "+f"(acc[a][nb][0]), "+f"(acc[a][nb][1]),
                          "+f"(acc[a][nb][2]), "+f"(acc[a][nb][3])
                        : "r"(afr[a][0]), "r"(afr[a][1]), "r"(afr[a][2]), "r"(afr[a][3]),
                          "r"(bfr[p][h*2]), "r"(bfr[p][h*2+1]));
                }

            if (c + 1 < NS) {               // stage into nxt buffers (safe: readers done)
                *(uint4*)(sAdst + nxt*2*128*SSTR + j*128*SSTR) = av;
                *(uint4*)(sBdst + nxt*2*128*SSTR + j*128*SSTR) = bv;
            }
        }
        __syncthreads();
    }

    // epilogue: cost = max(x2 + y2 - 2*dot, 0)
    float lmax = 0.f;
    #pragma unroll
    for (int a = 0; a < 4; a++) {
        int m0 = row0 + warpM*64 + a*16 + g;
        float x2a = g_x2[b*NN + m0];
        float x2b = g_x2[b*NN + m0 + 8];
        #pragma unroll
        for (int nb = 0; nb < 4; nb++) {
            int n0 = col0 + warpN*32 + nb*8 + tig*2;
            float y20 = g_y2[b*NN + n0];
            float y21 = g_y2[b*NN + n0 + 1];
            float c0 = fmaxf(x2a + y20 - 2.0f*acc[a][nb][0], 0.f);
            float c1 = fmaxf(x2a + y21 - 2.0f*acc[a][nb][1], 0.f);
            float c2 = fmaxf(x2b + y20 - 2.0f*acc[a][nb][2], 0.f);
            float c3 = fmaxf(x2b + y21 - 2.0f*acc[a][nb][3], 0.f);
            lmax = fmaxf(lmax, fmaxf(fmaxf(c0, c1), fmaxf(c2, c3)));
            *(float2*)&g_K[(size_t)(b*NN + m0)     * NN + n0] = make_float2(c0, c1);
            *(float2*)&g_K[(size_t)(b*NN + m0 + 8) * NN + n0] = make_float2(c2, c3);
        }
    }
    #pragma unroll
    for (int off = 16; off; off >>= 1) lmax = fmaxf(lmax, __shfl_xor_sync(0xffffffffu, lmax, off));
    if (lane == 0) atomicMax(&g_maxbits[b], __float_as_uint(lmax));
}

// ------ K = exp(-cost/(reg*max)) -> fp16 only --------------------------------
__global__ void exp_half_kernel() {
    const int total4 = BB * NN * NN / 4;
    const int per_b4 = NN * NN / 4;
    const float4* K4 = (const float4*)g_K;
    for (int i = blockIdx.x * blockDim.x + threadIdx.x; i < total4;
         i += gridDim.x * blockDim.x) {
        int b = i / per_b4;
        float s = -1.0f / (REG * __uint_as_float(g_maxbits[b]));
        float4 v = K4[i];
        v.x = __expf(v.x * s);
        v.y = __expf(v.y * s);
        v.z = __expf(v.z * s);
        v.w = __expf(v.w * s);
        __half2 h0 = __floats2half2_rn(v.x, v.y);
        __half2 h1 = __floats2half2_rn(v.z, v.w);
        *(uint2*)&g_Kh[(size_t)i * 4] = make_uint2(
            *(unsigned int*)&h0, *(unsigned int*)&h1);
    }
}

// ---------------- per-batch grid barrier -------------------------------------
__device__ __forceinline__ void batch_bar(int b, unsigned int target) {
    __threadfence();
    __syncthreads();
    if (threadIdx.x == 0) {
        atomicAdd(&g_barB[b], 1u);
        while (*(volatile unsigned int*)&g_barB[b] < target) __nanosleep(32);
        __threadfence();
    }
    __syncthreads();
}

// ---------------- fused persistent sinkhorn ----------------------------------
__global__ __launch_bounds__(256, 2) void sinkhorn_kernel() {
    __shared__ float sv[NN];
    __shared__ float sp[64];
    __shared__ float su[16];
    __shared__ float syA[NN];
    __shared__ float spr[256];
    int b = blockIdx.x >> 6;
    int q = blockIdx.x & 63;
    int t = threadIdx.x;
    int lane = t & 31, w = t >> 5;
    int wg = w >> 2;
    int ws = w & 3;
    int jA = ws*512 + lane*8;

    const __half* Kh = g_Kh + (size_t)b * NN * NN;
    unsigned int target = 0;

    for (int it = 0; it < NITER; ++it) {
        for (int j = t; j < NN; j += 256) sv[j] = __ldcg(&g_v[b*NN + j]);
        __syncthreads();
        float2 vv[2][4];
        #pragma unroll
        for (int p = 0; p < 2; p++)
            #pragma unroll
            for (int c = 0; c < 4; c++)
                vv[p][c] = *(const float2*)&sv[jA + p*256 + c*2];

        float yac[16];
        #pragma unroll
        for (int k = 0; k < 16; k++) yac[k] = 0.f;

        for (int s = q; s < 128; s += BPB) {
            const __half* Krow = Kh + (size_t)(s*16 + wg*8) * NN + jA;

            float acc[8];
            #pragma unroll
            for (int r = 0; r < 8; r++) acc[r] = 0.f;
            #pragma unroll
            for (int r = 0; r < 8; r++) {
                #pragma unroll
                for (int p = 0; p < 2; p++) {
                    uint4 kk = *(const uint4*)(Krow + (size_t)r * NN + p*256);
                    const __half2* h = (const __half2*)&kk;
                    #pragma unroll
                    for (int c = 0; c < 4; c++) {
                        float2 kf = __half22float2(h[c]);
                        acc[r] = fmaf(kf.x, vv[p][c].x, acc[r]);
                        acc[r] = fmaf(kf.y, vv[p][c].y, acc[r]);
                    }
                }
            }
            #pragma unroll
            for (int r = 0; r < 8; r++) {
                float sm = acc[r];
                #pragma unroll
                for (int off = 16; off; off >>= 1) sm += __shfl_xor_sync(0xffffffffu, sm, off);
                if (lane == 0) sp[(wg*8 + r)*4 + ws] = sm;
            }
            __syncthreads();
            if (t < 16) {
                float tot = sp[t*4] + sp[t*4+1] + sp[t*4+2] + sp[t*4+3];
                float uu = powf(A0 / tot, FI);
                su[t] = uu;
                g_u[b*NN + s*16 + t] = uu;
            }
            __syncthreads();

            float ur[8];
            #pragma unroll
            for (int r = 0; r < 8; r++) ur[r] = su[wg*8 + r];
            #pragma unroll
            for (int r = 0; r < 8; r++) {
                #pragma unroll
                for (int p = 0; p < 2; p++) {
                    uint4 kk = *(const uint4*)(Krow + (size_t)r * NN + p*256);
                    const __half2* h = (const __half2*)&kk;
                    #pragma unroll
                    for (int c = 0; c < 4; c++) {
                        float2 kf = __half22float2(h[c]);
                        yac[p*8 + c*2]     = fmaf(kf.x, ur[r], yac[p*8 + c*2]);
                        yac[p*8 + c*2 + 1] = fmaf(kf.y, ur[r], yac[p*8 + c*2 + 1]);
                    }
                }
            }
        }

        if (wg == 1) {
            #pragma unroll
            for (int p = 0; p < 2; p++)
                #pragma unroll
                for (int c = 0; c < 4; c++)
                    *(float2*)&syA[jA + p*256 + c*2] = *(float2*)&yac[p*8 + c*2];
        }
        __syncthreads();
        if (wg == 0) {
            float* dst = g_part + ((size_t)(b*BPB + q)) * NN;
            #pragma unroll
            for (int p = 0; p < 2; p++)
                #pragma unroll
                for (int c = 0; c < 4; c++) {
                    int col = jA + p*256 + c*2;
                    float2 yy = *(float2*)&yac[p*8 + c*2];
                    float2 zz = *(float2*)&syA[col];
                    yy.x += zz.x; yy.y += zz.y;
                    *(float2*)&dst[col] = yy;
                }
        }
        target += BPB;
        batch_bar(b, target);

        {
            int col = q*32 + lane;
            float sm = 0.f;
            #pragma unroll
            for (int k = 0; k < 8; k++)
                sm += __ldcg(&g_part[((size_t)(b*BPB + w + 8*k)) * NN + col]);
            spr[w*32 + lane] = sm;
            __syncthreads();
            if (t < 32) {
                float tot = 0.f;
                #pragma unroll
                for (int p = 0; p < 8; p++) tot += spr[p*32 + t];
                g_v[b*NN + q*32 + t] = powf(A0 / tot, FI);
            }
        }
        target += BPB;
        batch_bar(b, target);
    }
}

// ------ out[b][j][i] = u[i] Kh[i][j] v[j]  (fp16 K read, 32x32 transpose) ----
__global__ void output_kernel(float* __restrict__ out) {
    __shared__ float tile[32][33];
    int b  = blockIdx.z;
    int j0 = blockIdx.x * 32;
    int i0 = blockIdx.y * 32;
    int tx = threadIdx.x, ty = threadIdx.y;
    const __half* Kb = g_Kh + (size_t)b * NN * NN;
    float vj = g_v[b*NN + j0 + tx];
    #pragma unroll
    for (int k = 0; k < 4; k++) {
        int i = i0 + ty + 8*k;
        float kij = __half2float(Kb[(size_t)i * NN + j0 + tx]);
        tile[ty + 8*k][tx] = kij * g_u[b*NN + i] * vj;
    }
    __syncthreads();
    #pragma unroll
    for (int k = 0; k < 4; k++) {
        int j = j0 + ty + 8*k;
        out[((size_t)b*NN + j) * NN + i0 + tx] = tile[tx][ty + 8*k];
    }
}

// ---------------- launch ------------------------------------------------------
extern "C" void kernel_launch(void* const* d_in, const int* in_sizes, int n_in,
                              void* d_out, int out_size) {
    const float* x = (const float*)d_in[0];
    const float* y = (const float*)d_in[1];
    float* out = (float*)d_out;

    init_kernel<<<(BB*NN + 255)/256, 256>>>();
    normalize_rows<<<BB*NN, 128>>>(x, 0);
    normalize_rows<<<BB*NN, 128>>>(y, 1);

    dim3 gcost(NN/128, NN/128, BB);
    cost_mma_kernel<<<gcost, 256>>>();

    exp_half_kernel<<<4096, 256>>>();

    sinkhorn_kernel<<<GRID, 256>>>();

    dim3 gout(NN/32, NN/32, BB);
    output_kernel<<<gout, dim3(32, 8)>>>(out);
}

// round 15
// speedup vs baseline: 1.1188x; 1.0449x over previous
#include <cuda_runtime.h>
#include <cuda_fp16.h>
#include <cuda_bf16.h>
#include <math.h>

#define BB 4
#define NN 2048
#define DD 512
#define KC 1536                        // concat K = 3*DD for split-bf16 GEMM
#define REG 0.1f
#define NITER 20
#define BPB 64
#define GRID (BB*BPB)

#define FI 0.83333333333333337f
#define A0 (1.0f/2048.0f)
#define V0 (1.0f/2048.0f)

#define SSTR 24                        // smem row stride (bf16 elems): conflict-free LDSM

// ---------------- scratch ----------------------------------------------------
__device__ __nv_bfloat16 g_xc[(size_t)BB*NN*KC];  // [xh | xl | xh]
__device__ __nv_bfloat16 g_yc[(size_t)BB*NN*KC];  // [yh | yh | yl]
__device__ float  g_x2[BB*NN];
__device__ float  g_y2[BB*NN];
__device__ float  g_K  [(size_t)BB*NN*NN];  // fp32 cost (cost_mma -> sinkhorn iter0)
__device__ __half g_Kh [(size_t)BB*NN*NN];  // fp16 K (sinkhorn + output)
__device__ float  g_part[(size_t)BB*BPB*NN];
__device__ float  g_u [BB*NN];
__device__ float  g_v [BB*NN];
__device__ unsigned int g_maxbits[BB];
__device__ unsigned int g_barB[BB];

// ---------------- init -------------------------------------------------------
__global__ void init_kernel() {
    int i = blockIdx.x * blockDim.x + threadIdx.x;
    if (i < BB) { g_maxbits[i] = 0u; g_barB[i] = 0u; }
    if (i < BB*NN) g_v[i] = V0;
}

// -------- per-row min-shift + sumsq + bf16 hi/lo split ------------------------
__global__ void normalize_rows(const float* __restrict__ src, int sel) {
    int row = blockIdx.x;
    const float* r = src + (size_t)row * DD;
    __nv_bfloat16* cat = (sel ? g_yc : g_xc) + (size_t)row * KC;
    float* sq = (sel ? g_y2 : g_x2);
    int t = threadIdx.x;
    float v[4];
    float mn = 3.0e38f;
    #pragma unroll
    for (int k = 0; k < 4; k++) { v[k] = r[t + 128*k]; mn = fminf(mn, v[k]); }
    #pragma unroll
    for (int off = 16; off; off >>= 1) mn = fminf(mn, __shfl_xor_sync(0xffffffffu, mn, off));
    __shared__ float smn[4];
    __shared__ float sss[4];
    int w = t >> 5;
    if ((t & 31) == 0) smn[w] = mn;
    __syncthreads();
    mn = fminf(fminf(smn[0], smn[1]), fminf(smn[2], smn[3]));
    float ss = 0.f;
    #pragma unroll
    for (int k = 0; k < 4; k++) {
        float z = v[k] - mn;
        ss += z*z;
        __nv_bfloat16 hi = __float2bfloat16(z);
        __nv_bfloat16 lo = __float2bfloat16(z - __bfloat162float(hi));
        int col = t + 128*k;
        if (sel == 0) { cat[col] = hi; cat[DD + col] = lo; cat[2*DD + col] = hi; }
        else          { cat[col] = hi; cat[DD + col] = hi; cat[2*DD + col] = lo; }
    }
    #pragma unroll
    for (int off = 16; off; off >>= 1) ss += __shfl_xor_sync(0xffffffffu, ss, off);
    if ((t & 31) == 0) sss[w] = ss;
    __syncthreads();
    if (t == 0) sq[row] = sss[0] + sss[1] + sss[2] + sss[3];
}

// -------- cost GEMM via mma.sync bf16 (split-precision, K=1536) --------------
// R12-proven geometry: block 128x128, 8 warps (2x4) of 64x32, k-step 16.
__global__ __launch_bounds__(256) void cost_mma_kernel() {
    __shared__ __align__(16) unsigned short sA[2][128*SSTR];
    __shared__ __align__(16) unsigned short sB[2][128*SSTR];
    int b    = blockIdx.z;
    int col0 = blockIdx.x * 128;
    int row0 = blockIdx.y * 128;
    int t    = threadIdx.x;
    int lane = t & 31, wid = t >> 5;
    int warpM = wid >> 2, warpN = wid & 3;   // 2 x 4
    int g = lane >> 2, tig = lane & 3;

    const __nv_bfloat16* Agl = g_xc + (size_t)(b*NN + row0) * KC;
    const __nv_bfloat16* Bgl = g_yc + (size_t)(b*NN + col0) * KC;

    int srow = t >> 1;
    int skof = (t & 1) * 8;
    const uint4* Ap = (const uint4*)(Agl + (size_t)srow * KC + skof);
    const uint4* Bp = (const uint4*)(Bgl + (size_t)srow * KC + skof);
    unsigned short* sAdst = &sA[0][0] + srow*SSTR + skof;
    unsigned short* sBdst = &sB[0][0] + srow*SSTR + skof;

    int arow = warpM*64 + (lane & 7) + ((lane >> 3) & 1) * 8;
    int acol = (lane >> 4) * 8;
    unsigned aoff0 = (unsigned)__cvta_generic_to_shared(&sA[0][0]) + (arow*SSTR + acol)*2;
    int brow = warpN*32 + (lane >> 4) * 8 + (lane & 7);
    int bcol = ((lane >> 3) & 1) * 8;
    unsigned boff0 = (unsigned)__cvta_generic_to_shared(&sB[0][0]) + (brow*SSTR + bcol)*2;
    const unsigned STGB = 128*SSTR*2;

    float acc[4][4][4];
    #pragma unroll
    for (int a = 0; a < 4; a++)
        #pragma unroll
        for (int nb = 0; nb < 4; nb++)
            #pragma unroll
            for (int e = 0; e < 4; e++) acc[a][nb][e] = 0.f;

    uint4 av = Ap[0], bv = Bp[0];
    *(uint4*)sAdst = av;
    *(uint4*)sBdst = bv;
    __syncthreads();

    const int NK = KC / 16;    // 96
    for (int c = 0; c < NK; c++) {
        int cur = c & 1, nxt = cur ^ 1;
        if (c + 1 < NK) {
            av = Ap[(c+1)*2];
            bv = Bp[(c+1)*2];
        }
        unsigned abase = aoff0 + cur*STGB;
        unsigned bbase = boff0 + cur*STGB;

        unsigned afr[4][4], bfr[2][4];
        #pragma unroll
        for (int a = 0; a < 4; a++) {
            unsigned ad = abase + a*16*SSTR*2;
            asm volatile("ldmatrix.sync.aligned.m8n8.x4.shared.b16 {%0,%1,%2,%3}, [%4];"
                : "=r"(afr[a][0]), "=r"(afr[a][1]), "=r"(afr[a][2]), "=r"(afr[a][3])
                : "r"(ad));
        }
        #pragma unroll
        for (int p = 0; p < 2; p++) {
            unsigned bd = bbase + p*16*SSTR*2;
            asm volatile("ldmatrix.sync.aligned.m8n8.x4.shared.b16 {%0,%1,%2,%3}, [%4];"
                : "=r"(bfr[p][0]), "=r"(bfr[p][1]), "=r"(bfr[p][2]), "=r"(bfr[p][3])
                : "r"(bd));
        }
        #pragma unroll
        for (int a = 0; a < 4; a++)
            #pragma unroll
            for (int nb = 0; nb < 4; nb++) {
                int p = nb >> 1, h = nb & 1;
                asm volatile(
                    "mma.sync.aligned.m16n8k16.row.col.f32.bf16.bf16.f32 "
                    "{%0,%1,%2,%3}, {%4,%5,%6,%7}, {%8,%9}, {%0,%1,%2,%3};"
                    : "+f"(acc[a][nb][0]), "+f"(acc[a][nb][1]),
                      "+f"(acc[a][nb][2]), "+f"(acc[a][nb][3])
                    : "r"(afr[a][0]), "r"(afr[a][1]), "r"(afr[a][2]), "r"(afr[a][3]),
                      "r"(bfr[p][h*2]), "r"(bfr[p][h*2+1]));
            }

        if (c + 1 < NK) {
            *(uint4*)(sAdst + nxt*128*SSTR) = av;
            *(uint4*)(sBdst + nxt*128*SSTR) = bv;
        }
        __syncthreads();
    }

    float lmax = 0.f;
    #pragma unroll
    for (int a = 0; a < 4; a++) {
        int m0 = row0 + warpM*64 + a*16 + g;
        float x2a = g_x2[b*NN + m0];
        float x2b = g_x2[b*NN + m0 + 8];
        #pragma unroll
        for (int nb = 0; nb < 4; nb++) {
            int n0 = col0 + warpN*32 + nb*8 + tig*2;
            float y20 = g_y2[b*NN + n0];
            float y21 = g_y2[b*NN + n0 + 1];
            float c0 = fmaxf(x2a + y20 - 2.0f*acc[a][nb][0], 0.f);
            float c1 = fmaxf(x2a + y21 - 2.0f*acc[a][nb][1], 0.f);
            float c2 = fmaxf(x2b + y20 - 2.0f*acc[a][nb][2], 0.f);
            float c3 = fmaxf(x2b + y21 - 2.0f*acc[a][nb][3], 0.f);
            lmax = fmaxf(lmax, fmaxf(fmaxf(c0, c1), fmaxf(c2, c3)));
            *(float2*)&g_K[(size_t)(b*NN + m0)     * NN + n0] = make_float2(c0, c1);
            *(float2*)&g_K[(size_t)(b*NN + m0 + 8) * NN + n0] = make_float2(c2, c3);
        }
    }
    #pragma unroll
    for (int off = 16; off; off >>= 1) lmax = fmaxf(lmax, __shfl_xor_sync(0xffffffffu, lmax, off));
    if (lane == 0) atomicMax(&g_maxbits[b], __float_as_uint(lmax));
}

// ---------------- per-batch grid barrier -------------------------------------
__device__ __forceinline__ void batch_bar(int b, unsigned int target) {
    __threadfence();
    __syncthreads();
    if (threadIdx.x == 0) {
        atomicAdd(&g_barB[b], 1u);
        while (*(volatile unsigned int*)&g_barB[b] < target) __nanosleep(32);
        __threadfence();
    }
    __syncthreads();
}

// ---------------- fused persistent sinkhorn (exp fused into iter 0) ----------
__global__ __launch_bounds__(256, 2) void sinkhorn_kernel() {
    __shared__ float sv[NN];
    __shared__ float sp[64];
    __shared__ float su[16];
    __shared__ float syA[NN];
    __shared__ float spr[256];
    int b = blockIdx.x >> 6;
    int q = blockIdx.x & 63;
    int t = threadIdx.x;
    int lane = t & 31, w = t >> 5;
    int wg = w >> 2;
    int ws = w & 3;
    int jA = ws*512 + lane*8;

    const __half* Kh = g_Kh + (size_t)b * NN * NN;
    __half*       KhW = g_Kh + (size_t)b * NN * NN;
    const float*  Kf  = g_K  + (size_t)b * NN * NN;
    float s_scale = -1.0f / (REG * __uint_as_float(g_maxbits[b]));
    unsigned int target = 0;

    for (int it = 0; it < NITER; ++it) {
        float2 vv[2][4];
        if (it > 0) {
            for (int j = t; j < NN; j += 256) sv[j] = __ldcg(&g_v[b*NN + j]);
            __syncthreads();
            #pragma unroll
            for (int p = 0; p < 2; p++)
                #pragma unroll
                for (int c = 0; c < 4; c++)
                    vv[p][c] = *(const float2*)&sv[jA + p*256 + c*2];
        }

        float yac[16];
        #pragma unroll
        for (int k = 0; k < 16; k++) yac[k] = 0.f;

        for (int s = q; s < 128; s += BPB) {
            const __half* Krow = Kh + (size_t)(s*16 + wg*8) * NN + jA;

            // pass 1: row dots -> u for the 16 rows of this stripe
            float acc[8];
            #pragma unroll
            for (int r = 0; r < 8; r++) acc[r] = 0.f;
            if (it == 0) {
                // fused exp: read fp32 cost, compute K=exp, write fp16, row-sum (v=V0)
                #pragma unroll
                for (int r = 0; r < 8; r++) {
                    const float* KfRow = Kf + (size_t)(s*16 + wg*8 + r) * NN + jA;
                    __half* KhRow = KhW + (size_t)(s*16 + wg*8 + r) * NN + jA;
                    #pragma unroll
                    for (int p = 0; p < 2; p++) {
                        float4 ca = *(const float4*)(KfRow + p*256);
                        float4 cb = *(const float4*)(KfRow + p*256 + 4);
                        float e0 = __expf(ca.x*s_scale), e1 = __expf(ca.y*s_scale);
                        float e2 = __expf(ca.z*s_scale), e3 = __expf(ca.w*s_scale);
                        float e4 = __expf(cb.x*s_scale), e5 = __expf(cb.y*s_scale);
                        float e6 = __expf(cb.z*s_scale), e7 = __expf(cb.w*s_scale);
                        acc[r] += (e0+e1+e2+e3) + (e4+e5+e6+e7);
                        __half2 h0 = __floats2half2_rn(e0, e1);
                        __half2 h1 = __floats2half2_rn(e2, e3);
                        __half2 h2 = __floats2half2_rn(e4, e5);
                        __half2 h3 = __floats2half2_rn(e6, e7);
                        uint4 pk = make_uint4(*(unsigned*)&h0, *(unsigned*)&h1,
                                              *(unsigned*)&h2, *(unsigned*)&h3);
                        *(uint4*)(KhRow + p*256) = pk;
                    }
                    acc[r] *= V0;   // v uniform on iteration 0
                }
            } else {
                #pragma unroll
                for (int r = 0; r < 8; r++) {
                    #pragma unroll
                    for (int p = 0; p < 2; p++) {
                        uint4 kk = *(const uint4*)(Krow + (size_t)r * NN + p*256);
                        const __half2* h = (const __half2*)&kk;
                        #pragma unroll
                        for (int c = 0; c < 4; c++) {
                            float2 kf = __half22float2(h[c]);
                            acc[r] = fmaf(kf.x, vv[p][c].x, acc[r]);
                            acc[r] = fmaf(kf.y, vv[p][c].y, acc[r]);
                        }
                    }
                }
            }
            #pragma unroll
            for (int r = 0; r < 8; r++) {
                float sm = acc[r];
                #pragma unroll
                for (int off = 16; off; off >>= 1) sm += __shfl_xor_sync(0xffffffffu, sm, off);
                if (lane == 0) sp[(wg*8 + r)*4 + ws] = sm;
            }
            __syncthreads();
            if (t < 16) {
                float tot = sp[t*4] + sp[t*4+1] + sp[t*4+2] + sp[t*4+3];
                float uu = powf(A0 / tot, FI);
                su[t] = uu;
                g_u[b*NN + s*16 + t] = uu;
            }
            __syncthreads();

            // pass 2: re-walk rows (Kh; iter0 reads values this thread just wrote)
            float ur[8];
            #pragma unroll
            for (int r = 0; r < 8; r++) ur[r] = su[wg*8 + r];
            #pragma unroll
            for (int r = 0; r < 8; r++) {
                #pragma unroll
                for (int p = 0; p < 2; p++) {
                    uint4 kk = *(const uint4*)(Krow + (size_t)r * NN + p*256);
                    const __half2* h = (const __half2*)&kk;
                    #pragma unroll
                    for (int c = 0; c < 4; c++) {
                        float2 kf = __half22float2(h[c]);
                        yac[p*8 + c*2]     = fmaf(kf.x, ur[r], yac[p*8 + c*2]);
                        yac[p*8 + c*2 + 1] = fmaf(kf.y, ur[r], yac[p*8 + c*2 + 1]);
                    }
                }
            }
        }

        if (wg == 1) {
            #pragma unroll
            for (int p = 0; p < 2; p++)
                #pragma unroll
                for (int c = 0; c < 4; c++)
                    *(float2*)&syA[jA + p*256 + c*2] = *(float2*)&yac[p*8 + c*2];
        }
        __syncthreads();
        if (wg == 0) {
            float* dst = g_part + ((size_t)(b*BPB + q)) * NN;
            #pragma unroll
            for (int p = 0; p < 2; p++)
                #pragma unroll
                for (int c = 0; c < 4; c++) {
                    int col = jA + p*256 + c*2;
                    float2 yy = *(float2*)&yac[p*8 + c*2];
                    float2 zz = *(float2*)&syA[col];
                    yy.x += zz.x; yy.y += zz.y;
                    *(float2*)&dst[col] = yy;
                }
        }
        target += BPB;
        batch_bar(b, target);

        {
            int col = q*32 + lane;
            float sm = 0.f;
            #pragma unroll
            for (int k = 0; k < 8; k++)
                sm += __ldcg(&g_part[((size_t)(b*BPB + w + 8*k)) * NN + col]);
            spr[w*32 + lane] = sm;
            __syncthreads();
            if (t < 32) {
                float tot = 0.f;
                #pragma unroll
                for (int p = 0; p < 8; p++) tot += spr[p*32 + t];
                g_v[b*NN + q*32 + t] = powf(A0 / tot, FI);
            }
        }
        target += BPB;
        batch_bar(b, target);
    }
}

// ------ out[b][j][i] = u[i] Kh[i][j] v[j]  (fp16 K read, 32x32 transpose) ----
__global__ void output_kernel(float* __restrict__ out) {
    __shared__ float tile[32][33];
    int b  = blockIdx.z;
    int j0 = blockIdx.x * 32;
    int i0 = blockIdx.y * 32;
    int tx = threadIdx.x, ty = threadIdx.y;
    const __half* Kb = g_Kh + (size_t)b * NN * NN;
    float vj = g_v[b*NN + j0 + tx];
    #pragma unroll
    for (int k = 0; k < 4; k++) {
        int i = i0 + ty + 8*k;
        float kij = __half2float(Kb[(size_t)i * NN + j0 + tx]);
        tile[ty + 8*k][tx] = kij * g_u[b*NN + i] * vj;
    }
    __syncthreads();
    #pragma unroll
    for (int k = 0; k < 4; k++) {
        int j = j0 + ty + 8*k;
        out[((size_t)b*NN + j) * NN + i0 + tx] = tile[tx][ty + 8*k];
    }
}

// ---------------- launch ------------------------------------------------------
extern "C" void kernel_launch(void* const* d_in, const int* in_sizes, int n_in,
                              void* d_out, int out_size) {
    const float* x = (const float*)d_in[0];
    const float* y = (const float*)d_in[1];
    float* out = (float*)d_out;

    init_kernel<<<(BB*NN + 255)/256, 256>>>();
    normalize_rows<<<BB*NN, 128>>>(x, 0);
    normalize_rows<<<BB*NN, 128>>>(y, 1);

    dim3 gcost(NN/128, NN/128, BB);
    cost_mma_kernel<<<gcost, 256>>>();

    sinkhorn_kernel<<<GRID, 256>>>();

    dim3 gout(NN/32, NN/32, BB);
    output_kernel<<<gout, dim3(32, 8)>>>(out);
}